// round 4
// baseline (speedup 1.0000x reference)
#include <cuda_runtime.h>
#include <cstdint>

// Bilinear resample: B=16, S=128, C=128, fp32.
// R4: cp.async (LDGSTS) double-buffered pipeline. Gathered 512B corner rows
// land in SMEM (no register pressure), 2 pipeline stages per warp keep
// ~4KB/warp of loads in flight. Each lane consumes exactly the bytes it
// copied -> no block/warp barriers needed.

#define S 128
#define C 128
#define C4 (C / 4)                 // float4s per pixel
#define NPIX (16 * S * S)          // 262144
#define NPAIR (NPIX / 2)           // 131072 pixel pairs
#define WARPS_PER_CTA 4
#define CTAS 1024
#define PAIRS_PER_WARP (NPAIR / (CTAS * WARPS_PER_CTA))  // 32
#define DEPTH 2

__device__ __forceinline__ uint32_t smem_u32(const void* p) {
    return (uint32_t)__cvta_generic_to_shared(p);
}

__device__ __forceinline__ void cp_async16(uint32_t saddr, const void* gaddr) {
    asm volatile("cp.async.ca.shared.global [%0], [%1], 16;\n"
                 :: "r"(saddr), "l"(gaddr));
}

__device__ __forceinline__ void cp_commit() {
    asm volatile("cp.async.commit_group;\n");
}

template <int N>
__device__ __forceinline__ void cp_wait() {
    asm volatile("cp.async.wait_group %0;\n" :: "n"(N));
}

__global__ __launch_bounds__(128) void resample_kernel(
    const float* __restrict__ offsets,
    const float* __restrict__ inputs,
    float* __restrict__ out)
{
    // [warp][stage][corner 0..7][lane] ; corners 0-3 = pixel A, 4-7 = pixel B.
    __shared__ float4 buf[WARPS_PER_CTA][DEPTH][8][32];   // 32 KB

    const int lane = threadIdx.x & 31;
    const int wib  = threadIdx.x >> 5;
    const int wg   = blockIdx.x * WARPS_PER_CTA + wib;
    const int pbase = wg * PAIRS_PER_WARP;

    const float4* off4 = reinterpret_cast<const float4*>(offsets);
    const float4* in4  = reinterpret_cast<const float4*>(inputs);
    float4*       out4 = reinterpret_cast<float4*>(out);

    // ---- coordinate helper (matches reference semantics) ----
    // returns packed y0,x0,y1,x1 and fractions
    auto coords = [&](float offy, float offx, int i, int j,
                      int& y0, int& x0, int& y1, int& x1,
                      float& fy, float& fx) {
        const float y = fminf(fmaxf(offy + (float)i, 0.0f), (float)(S - 1));
        const float x = fminf(fmaxf(offx + (float)j, 0.0f), (float)(S - 1));
        const float y0f = floorf(y);
        const float x0f = floorf(x);
        y0 = (int)y0f;  x0 = (int)x0f;
        y1 = (int)ceilf(y);  x1 = (int)ceilf(x);
        fy = y - y0f;        // row fraction
        fx = x - x0f;        // col fraction
    };

    auto prefetch = [&](int p, int s) {
        const float4 off2 = __ldg(off4 + p);          // both pixels' (dy,dx)
        const int pix0 = p * 2;
        const int j0 = pix0 & (S - 1);
        const int i  = (pix0 >> 7) & (S - 1);
        const int b  = pix0 >> 14;
        const float4* base = in4 + (size_t)b * (S * S * C4);

        int y0, x0, y1, x1; float fy, fx;
        // pixel A
        coords(off2.x, off2.y, i, j0, y0, x0, y1, x1, fy, fx);
        cp_async16(smem_u32(&buf[wib][s][0][lane]), base + (y0 * S + x0) * C4 + lane);
        cp_async16(smem_u32(&buf[wib][s][1][lane]), base + (y0 * S + x1) * C4 + lane);
        cp_async16(smem_u32(&buf[wib][s][2][lane]), base + (y1 * S + x0) * C4 + lane);
        cp_async16(smem_u32(&buf[wib][s][3][lane]), base + (y1 * S + x1) * C4 + lane);
        // pixel B
        coords(off2.z, off2.w, i, j0 + 1, y0, x0, y1, x1, fy, fx);
        cp_async16(smem_u32(&buf[wib][s][4][lane]), base + (y0 * S + x0) * C4 + lane);
        cp_async16(smem_u32(&buf[wib][s][5][lane]), base + (y0 * S + x1) * C4 + lane);
        cp_async16(smem_u32(&buf[wib][s][6][lane]), base + (y1 * S + x0) * C4 + lane);
        cp_async16(smem_u32(&buf[wib][s][7][lane]), base + (y1 * S + x1) * C4 + lane);
        cp_commit();
    };

    auto lerp4 = [](float4 v00, float4 v01, float4 v10, float4 v11,
                    float fx, float fy) {
        float4 t, bo, o;
        t.x  = v00.x + (v01.x - v00.x) * fx;
        t.y  = v00.y + (v01.y - v00.y) * fx;
        t.z  = v00.z + (v01.z - v00.z) * fx;
        t.w  = v00.w + (v01.w - v00.w) * fx;
        bo.x = v10.x + (v11.x - v10.x) * fx;
        bo.y = v10.y + (v11.y - v10.y) * fx;
        bo.z = v10.z + (v11.z - v10.z) * fx;
        bo.w = v10.w + (v11.w - v10.w) * fx;
        o.x  = t.x + (bo.x - t.x) * fy;
        o.y  = t.y + (bo.y - t.y) * fy;
        o.z  = t.z + (bo.z - t.z) * fy;
        o.w  = t.w + (bo.w - t.w) * fy;
        return o;
    };

    auto consume = [&](int p, int s) {
        // Recompute fractions (broadcast L1-hit load; no cross-stage regs).
        const float4 off2 = __ldg(off4 + p);
        const int pix0 = p * 2;
        const int j0 = pix0 & (S - 1);
        const int i  = (pix0 >> 7) & (S - 1);

        int y0, x0, y1, x1; float fyA, fxA, fyB, fxB;
        coords(off2.x, off2.y, i, j0,     y0, x0, y1, x1, fyA, fxA);
        coords(off2.z, off2.w, i, j0 + 1, y0, x0, y1, x1, fyB, fxB);

        const float4 a00 = buf[wib][s][0][lane];
        const float4 a01 = buf[wib][s][1][lane];
        const float4 a10 = buf[wib][s][2][lane];
        const float4 a11 = buf[wib][s][3][lane];
        const float4 b00 = buf[wib][s][4][lane];
        const float4 b01 = buf[wib][s][5][lane];
        const float4 b10 = buf[wib][s][6][lane];
        const float4 b11 = buf[wib][s][7][lane];

        float4* outp = out4 + (size_t)pix0 * C4 + lane;
        outp[0]  = lerp4(a00, a01, a10, a11, fxA, fyA);
        outp[C4] = lerp4(b00, b01, b10, b11, fxB, fyB);
    };

    // ---- pipeline: 2-deep ----
    prefetch(pbase + 0, 0);
    prefetch(pbase + 1, 1);

#pragma unroll 2
    for (int k = 0; k < PAIRS_PER_WARP; k++) {
        const int s = k & 1;
        if (k + 1 < PAIRS_PER_WARP) cp_wait<1>();
        else                        cp_wait<0>();
        consume(pbase + k, s);
        if (k + 2 < PAIRS_PER_WARP) prefetch(pbase + k + 2, s);
    }
}

extern "C" void kernel_launch(void* const* d_in, const int* in_sizes, int n_in,
                              void* d_out, int out_size)
{
    const float* offsets = (const float*)d_in[0];
    const float* inputs  = (const float*)d_in[1];
    float* out = (float*)d_out;

    resample_kernel<<<CTAS, WARPS_PER_CTA * 32>>>(offsets, inputs, out);
}

// round 5
// speedup vs baseline: 1.5483x; 1.5483x over previous
#include <cuda_runtime.h>
#include <cstdint>

// Bilinear resample: B=16, S=128, C=128, fp32.
// R5: warp = pixel pair (8 coalesced 512B gathers, register-light like R2),
// looped over 8 consecutive pairs per warp, with prefetch.global.L2 of the
// pair-(k+2) corner rows issued at iteration k. Prefetch needs no dest regs,
// so MLP rises without the R3/R4 register/occupancy penalties.

#define S 128
#define C 128
#define C4 (C / 4)                  // float4s per pixel
#define NPIX (16 * S * S)           // 262144
#define NPAIR (NPIX / 2)            // 131072
#define PAIRS_PER_WARP 8
#define WARPS_PER_CTA 4
#define NBLOCKS (NPAIR / (PAIRS_PER_WARP * WARPS_PER_CTA))   // 4096, exact

__device__ __forceinline__ void l2_prefetch(const void* p) {
    asm volatile("prefetch.global.L2 [%0];" :: "l"(p));
}

// Compute the 4 corner row indices (in float4 units, lane-independent) and
// fractions for one pixel. Matches reference: rb=ceil, clip [0,S-1],
// col-fraction applied first, row-fraction second.
__device__ __forceinline__ void pixel_corners(
    float offy, float offx, int i, int j,
    int& i00, int& i01, int& i10, int& i11, float& fy, float& fx)
{
    const float y = fminf(fmaxf(offy + (float)i, 0.0f), (float)(S - 1));
    const float x = fminf(fmaxf(offx + (float)j, 0.0f), (float)(S - 1));
    const float y0f = floorf(y);
    const float x0f = floorf(x);
    const int y0 = (int)y0f;
    const int x0 = (int)x0f;
    const int y1 = (int)ceilf(y);
    const int x1 = (int)ceilf(x);
    fy = y - y0f;     // row fraction
    fx = x - x0f;     // col fraction
    i00 = (y0 * S + x0) * C4;
    i01 = (y0 * S + x1) * C4;
    i10 = (y1 * S + x0) * C4;
    i11 = (y1 * S + x1) * C4;
}

__device__ __forceinline__ float4 lerp4(float4 v00, float4 v01, float4 v10,
                                        float4 v11, float fx, float fy)
{
    float4 t, bo, o;
    t.x  = v00.x + (v01.x - v00.x) * fx;
    t.y  = v00.y + (v01.y - v00.y) * fx;
    t.z  = v00.z + (v01.z - v00.z) * fx;
    t.w  = v00.w + (v01.w - v00.w) * fx;
    bo.x = v10.x + (v11.x - v10.x) * fx;
    bo.y = v10.y + (v11.y - v10.y) * fx;
    bo.z = v10.z + (v11.z - v10.z) * fx;
    bo.w = v10.w + (v11.w - v10.w) * fx;
    o.x  = t.x + (bo.x - t.x) * fy;
    o.y  = t.y + (bo.y - t.y) * fy;
    o.z  = t.z + (bo.z - t.z) * fy;
    o.w  = t.w + (bo.w - t.w) * fy;
    return o;
}

__global__ __launch_bounds__(WARPS_PER_CTA * 32) void resample_kernel(
    const float* __restrict__ offsets,
    const float* __restrict__ inputs,
    float* __restrict__ out)
{
    const int lane = threadIdx.x & 31;
    const int w = blockIdx.x * WARPS_PER_CTA + (threadIdx.x >> 5);
    const int pbase = w * PAIRS_PER_WARP;

    const float4* off4 = reinterpret_cast<const float4*>(offsets);
    const float4* in4  = reinterpret_cast<const float4*>(inputs);
    float4*       out4 = reinterpret_cast<float4*>(out);

    // All 8 pairs share the same image row / batch (pbase..pbase+7 are
    // 16 consecutive pixels in one row: pbase*2 is a multiple of 16, row=128).
    const int pix00 = pbase * 2;
    const int j0 = pix00 & (S - 1);
    const int i  = (pix00 >> 7) & (S - 1);
    const int b  = pix00 >> 14;
    const float4* base = in4 + (size_t)b * (S * S * C4);

    // Lane -> (pixel, row, line) mapping for the combined prefetch:
    //   lane < 16 : pixel A ; lane >= 16 : pixel B
    //   row  = (lane >> 2) & 3  (00,01,10,11), line = lane & 3 (128B each)
    const int pf_row  = (lane >> 2) & 3;
    const int pf_line = lane & 3;

#pragma unroll
    for (int k = 0; k < PAIRS_PER_WARP; k++) {
        const int p = pbase + k;
        const int jA = j0 + 2 * k;

        // ---- prefetch pair k+2's 16 corner lines (one instruction) ----
        if (k + 2 < PAIRS_PER_WARP) {
            const float4 offp = __ldg(off4 + p + 2);     // L1 hit after k=0
            const int jP = j0 + 2 * (k + 2);
            int a00, a01, a10, a11, b00, b01, b10, b11;
            float dum0, dum1;
            pixel_corners(offp.x, offp.y, i, jP,     a00, a01, a10, a11, dum0, dum1);
            pixel_corners(offp.z, offp.w, i, jP + 1, b00, b01, b10, b11, dum0, dum1);
            // select my pixel's corner set, then my row within it
            const int r0 = (lane < 16) ? a00 : b00;
            const int r1 = (lane < 16) ? a01 : b01;
            const int r2 = (lane < 16) ? a10 : b10;
            const int r3 = (lane < 16) ? a11 : b11;
            const int rsel = (pf_row < 2) ? (pf_row == 0 ? r0 : r1)
                                          : (pf_row == 2 ? r2 : r3);
            l2_prefetch(reinterpret_cast<const char*>(base + rsel) + pf_line * 128);
        }

        // ---- gather + lerp + store pair k ----
        const float4 off2 = __ldg(off4 + p);
        int a00, a01, a10, a11, c00, c01, c10, c11;
        float fyA, fxA, fyB, fxB;
        pixel_corners(off2.x, off2.y, i, jA,     a00, a01, a10, a11, fyA, fxA);
        pixel_corners(off2.z, off2.w, i, jA + 1, c00, c01, c10, c11, fyB, fxB);

        const float4 vA00 = __ldg(base + a00 + lane);
        const float4 vA01 = __ldg(base + a01 + lane);
        const float4 vA10 = __ldg(base + a10 + lane);
        const float4 vA11 = __ldg(base + a11 + lane);
        const float4 vB00 = __ldg(base + c00 + lane);
        const float4 vB01 = __ldg(base + c01 + lane);
        const float4 vB10 = __ldg(base + c10 + lane);
        const float4 vB11 = __ldg(base + c11 + lane);

        float4* outp = out4 + (size_t)(p * 2) * C4 + lane;
        outp[0]  = lerp4(vA00, vA01, vA10, vA11, fxA, fyA);
        outp[C4] = lerp4(vB00, vB01, vB10, vB11, fxB, fyB);
    }
}

extern "C" void kernel_launch(void* const* d_in, const int* in_sizes, int n_in,
                              void* d_out, int out_size)
{
    const float* offsets = (const float*)d_in[0];
    const float* inputs  = (const float*)d_in[1];
    float* out = (float*)d_out;

    resample_kernel<<<NBLOCKS, WARPS_PER_CTA * 32>>>(offsets, inputs, out);
}

// round 6
// speedup vs baseline: 1.7468x; 1.1282x over previous
#include <cuda_runtime.h>

// Bilinear resample: B=16, S=128, C=128, fp32.
// R6: R2's proven warp=pixel-pair body (8 independent coalesced 512B
// gathers, low register count), but long-lived CTAs: grid=2048, each warp
// loops over 8 CONSECUTIVE pairs. All 8 offset pairs live in one 128B line
// -> one miss epoch then L1 hits; no per-CTA launch churn.

#define S 128
#define C 128
#define C4 (C / 4)                 // float4s per pixel
#define NPIX (16 * S * S)          // 262144
#define NPAIR (NPIX / 2)           // 131072
#define PAIRS_PER_WARP 8
#define WARPS_PER_CTA 8            // 256 threads
#define NBLOCKS (NPAIR / (PAIRS_PER_WARP * WARPS_PER_CTA))   // 2048, exact

__device__ __forceinline__ float4 lerp4(float4 v00, float4 v01, float4 v10,
                                        float4 v11, float fx, float fy)
{
    float4 t, bo, o;
    t.x  = v00.x + (v01.x - v00.x) * fx;
    t.y  = v00.y + (v01.y - v00.y) * fx;
    t.z  = v00.z + (v01.z - v00.z) * fx;
    t.w  = v00.w + (v01.w - v00.w) * fx;
    bo.x = v10.x + (v11.x - v10.x) * fx;
    bo.y = v10.y + (v11.y - v10.y) * fx;
    bo.z = v10.z + (v11.z - v10.z) * fx;
    bo.w = v10.w + (v11.w - v10.w) * fx;
    o.x  = t.x + (bo.x - t.x) * fy;
    o.y  = t.y + (bo.y - t.y) * fy;
    o.z  = t.z + (bo.z - t.z) * fy;
    o.w  = t.w + (bo.w - t.w) * fy;
    return o;
}

__global__ __launch_bounds__(256) void resample_kernel(
    const float* __restrict__ offsets,
    const float* __restrict__ inputs,
    float* __restrict__ out)
{
    const int lane = threadIdx.x & 31;
    const int w = blockIdx.x * WARPS_PER_CTA + (threadIdx.x >> 5);
    const int pbase = w * PAIRS_PER_WARP;

    const float4* off4 = reinterpret_cast<const float4*>(offsets);
    const float4* in4  = reinterpret_cast<const float4*>(inputs);
    float4*       out4 = reinterpret_cast<float4*>(out);

    // pbase*2 is a multiple of 16 -> all 8 pairs share row i and batch b.
    const int pix00 = pbase * 2;
    const int j0 = pix00 & (S - 1);
    const int i  = (pix00 >> 7) & (S - 1);
    const int b  = pix00 >> 14;
    const float4* base = in4 + (size_t)b * (S * S * C4);
    const float fi = (float)i;

#pragma unroll 1
    for (int k = 0; k < PAIRS_PER_WARP; k++) {
        const int p  = pbase + k;
        const int jA = j0 + 2 * k;

        // One 16B broadcast load; L1 hit for k>=1 (same 128B line).
        const float4 off2 = __ldg(off4 + p);

        // ---- pixel A coords (reference semantics: ceil for rb, clip) ----
        const float yA = fminf(fmaxf(off2.x + fi,              0.0f), (float)(S - 1));
        const float xA = fminf(fmaxf(off2.y + (float)jA,       0.0f), (float)(S - 1));
        // ---- pixel B coords ----
        const float yB = fminf(fmaxf(off2.z + fi,              0.0f), (float)(S - 1));
        const float xB = fminf(fmaxf(off2.w + (float)(jA + 1), 0.0f), (float)(S - 1));

        const float ay0f = floorf(yA), ax0f = floorf(xA);
        const float by0f = floorf(yB), bx0f = floorf(xB);
        const int aY0 = (int)ay0f,      aX0 = (int)ax0f;
        const int aY1 = (int)ceilf(yA), aX1 = (int)ceilf(xA);
        const int bY0 = (int)by0f,      bX0 = (int)bx0f;
        const int bY1 = (int)ceilf(yB), bX1 = (int)ceilf(xB);
        const float afy = yA - ay0f, afx = xA - ax0f;
        const float bfy = yB - by0f, bfx = xB - bx0f;

        // 8 independent coalesced 512B gathers.
        const float4 a00 = __ldg(base + (aY0 * S + aX0) * C4 + lane);
        const float4 a01 = __ldg(base + (aY0 * S + aX1) * C4 + lane);
        const float4 a10 = __ldg(base + (aY1 * S + aX0) * C4 + lane);
        const float4 a11 = __ldg(base + (aY1 * S + aX1) * C4 + lane);
        const float4 b00 = __ldg(base + (bY0 * S + bX0) * C4 + lane);
        const float4 b01 = __ldg(base + (bY0 * S + bX1) * C4 + lane);
        const float4 b10 = __ldg(base + (bY1 * S + bX0) * C4 + lane);
        const float4 b11 = __ldg(base + (bY1 * S + bX1) * C4 + lane);

        float4* outp = out4 + (size_t)(p * 2) * C4 + lane;
        outp[0]  = lerp4(a00, a01, a10, a11, afx, afy);
        outp[C4] = lerp4(b00, b01, b10, b11, bfx, bfy);
    }
}

extern "C" void kernel_launch(void* const* d_in, const int* in_sizes, int n_in,
                              void* d_out, int out_size)
{
    const float* offsets = (const float*)d_in[0];
    const float* inputs  = (const float*)d_in[1];
    float* out = (float*)d_out;

    resample_kernel<<<NBLOCKS, WARPS_PER_CTA * 32>>>(offsets, inputs, out);
}